// round 1
// baseline (speedup 1.0000x reference)
#include <cuda_runtime.h>
#include <math.h>

// Problem constants (fixed by the dataset)
#define E_NUM 32768
#define BATCH 128     // == H
#define DIM   1024    // IMG_DIM == TXT_DIM

// ---- device scratch (allocation-free: __device__ globals) ----
__device__ float g_imgT [DIM * BATCH];   // img^T  [i][b]
__device__ float g_txtT [DIM * BATCH];   // text^T [t][b]
__device__ float g_W1aT [BATCH * BATCH]; // W1[:, :128]^T  -> [b][j]
__device__ float g_W1bT [BATCH * BATCH]; // W1[:, 128:]^T  -> [b][j]
__device__ float g_UT   [DIM * BATCH];   // (W1a @ img + b1)^T : [s][j]
__device__ float g_VT   [DIM * BATCH];   // (W1b @ text)^T     : [t][j]
__device__ float g_oImgT[DIM * BATCH];   // attended_img^T [i][b]
__device__ float g_oTxtT[DIM * BATCH];   // attended_text^T [t][b]

// ---- zero the accumulators (graph replays need fresh zeros every launch) ----
__global__ void k_zero() {
    int i = blockIdx.x * blockDim.x + threadIdx.x;
    g_oImgT[i] = 0.0f;
    g_oTxtT[i] = 0.0f;
}

// ---- generic 32x32 tiled transpose: out[C_in][R_in] = in[R_in][C_in]^T ----
__global__ void k_transpose(const float* __restrict__ in, int in_stride,
                            float* __restrict__ out, int out_stride) {
    __shared__ float tile[32][33];
    int x = blockIdx.x * 32 + threadIdx.x;   // input col
    int y = blockIdx.y * 32 + threadIdx.y;   // input row
    tile[threadIdx.y][threadIdx.x] = in[(long)y * in_stride + x];
    __syncthreads();
    int ox = blockIdx.y * 32 + threadIdx.x;  // output col = input row
    int oy = blockIdx.x * 32 + threadIdx.y;  // output row = input col
    out[(long)oy * out_stride + ox] = tile[threadIdx.x][threadIdx.y];
}

// ---- UT[s][j] = b1[j] + sum_b W1aT[b][j]*imgT[s][b]
//      VT[t][j] =         sum_b W1bT[b][j]*txtT[t][b]
// One block (128 threads) per output row; W1*T reads are coalesced across j
// and stay hot in L1/L2 (64KB each).
__global__ void k_uv(const float* __restrict__ b1) {
    int  col = blockIdx.x & (DIM - 1);
    bool isV = blockIdx.x >= DIM;
    int  j   = threadIdx.x;

    const float* x  = (isV ? g_txtT : g_imgT) + col * BATCH;
    const float* Wt =  isV ? g_W1bT : g_W1aT;

    __shared__ float xs[BATCH];
    xs[j] = x[j];
    __syncthreads();

    float acc = isV ? 0.0f : b1[j];
#pragma unroll 16
    for (int b = 0; b < BATCH; ++b)
        acc = fmaf(Wt[b * BATCH + j], xs[b], acc);

    (isV ? g_VT : g_UT)[col * BATCH + j] = acc;
}

// ---- per-edge: a = sigmoid(w2 . relu(UT[s] + VT[t]) + b2), then scatter:
//      oImgT[s][:] += a * txtT[t][:];  oTxtT[t][:] += a * imgT[s][:]
// One warp per edge; 4 floats per lane (float4). 8 edges / 256-thread block.
__global__ void k_edge(const int* __restrict__ src, const int* __restrict__ tgt,
                       const float* __restrict__ w2, const float* __restrict__ b2) {
    int warp = threadIdx.x >> 5;
    int lane = threadIdx.x & 31;
    int e    = blockIdx.x * 8 + warp;

    int s = src[e];
    int t = tgt[e];

    float4 u = reinterpret_cast<const float4*>(g_UT + s * BATCH)[lane];
    float4 v = reinterpret_cast<const float4*>(g_VT + t * BATCH)[lane];
    float4 w = reinterpret_cast<const float4*>(w2)[lane];

    float h0 = fmaxf(u.x + v.x, 0.0f);
    float h1 = fmaxf(u.y + v.y, 0.0f);
    float h2 = fmaxf(u.z + v.z, 0.0f);
    float h3 = fmaxf(u.w + v.w, 0.0f);

    float p = fmaf(h0, w.x, fmaf(h1, w.y, fmaf(h2, w.z, h3 * w.w)));
#pragma unroll
    for (int off = 16; off; off >>= 1)
        p += __shfl_xor_sync(0xffffffffu, p, off);

    float a = 1.0f / (1.0f + expf(-(p + b2[0])));

    float4 tx = reinterpret_cast<const float4*>(g_txtT + t * BATCH)[lane];
    float4 im = reinterpret_cast<const float4*>(g_imgT + s * BATCH)[lane];

    float* oi = g_oImgT + s * BATCH + lane * 4;
    float* ot = g_oTxtT + t * BATCH + lane * 4;
    atomicAdd(oi + 0, a * tx.x);
    atomicAdd(oi + 1, a * tx.y);
    atomicAdd(oi + 2, a * tx.z);
    atomicAdd(oi + 3, a * tx.w);
    atomicAdd(ot + 0, a * im.x);
    atomicAdd(ot + 1, a * im.y);
    atomicAdd(ot + 2, a * im.z);
    atomicAdd(ot + 3, a * im.w);
}

// ---- final transpose of accumulators into the output layout ----
__global__ void k_writeout(float* __restrict__ out) {
    // out[0 .. 128*1024)        = attended_img  [b][i] = oImgT[i][b]
    // out[128*1024 .. 2*128*1024) = attended_text [b][t] = oTxtT[t][b]
    __shared__ float tile[32][33];
    bool second = blockIdx.z != 0;
    const float* in = second ? g_oTxtT : g_oImgT;
    float* o = out + (second ? (size_t)BATCH * DIM : 0);

    int x = blockIdx.x * 32 + threadIdx.x;   // b  (input col, 0..127)
    int y = blockIdx.y * 32 + threadIdx.y;   // i/t (input row, 0..1023)
    tile[threadIdx.y][threadIdx.x] = in[(long)y * BATCH + x];
    __syncthreads();
    int ox = blockIdx.y * 32 + threadIdx.x;  // i/t
    int oy = blockIdx.x * 32 + threadIdx.y;  // b
    o[(long)oy * DIM + ox] = tile[threadIdx.x][threadIdx.y];
}

extern "C" void kernel_launch(void* const* d_in, const int* in_sizes, int n_in,
                              void* d_out, int out_size) {
    const float* img = (const float*)d_in[0];   // [128, 1024]
    const float* txt = (const float*)d_in[1];   // [128, 1024]
    const int*   src = (const int*)  d_in[2];   // [32768]
    const int*   tgt = (const int*)  d_in[3];   // [32768]
    const float* W1  = (const float*)d_in[4];   // [128, 256]
    const float* b1  = (const float*)d_in[5];   // [128]
    const float* w2  = (const float*)d_in[6];   // [128]
    const float* b2  = (const float*)d_in[7];   // [1]
    float* out = (float*)d_out;                 // [2 * 128 * 1024]

    float *p_imgT, *p_txtT, *p_W1aT, *p_W1bT;
    cudaGetSymbolAddress((void**)&p_imgT, g_imgT);
    cudaGetSymbolAddress((void**)&p_txtT, g_txtT);
    cudaGetSymbolAddress((void**)&p_W1aT, g_W1aT);
    cudaGetSymbolAddress((void**)&p_W1bT, g_W1bT);

    dim3 tb(32, 32);

    // 0) zero accumulators
    k_zero<<<(DIM * BATCH) / 256, 256>>>();

    // 1) transposes: features -> [dim][batch], W1 halves -> [b][j]
    k_transpose<<<dim3(DIM / 32, BATCH / 32), tb>>>(img,        DIM, p_imgT, BATCH);
    k_transpose<<<dim3(DIM / 32, BATCH / 32), tb>>>(txt,        DIM, p_txtT, BATCH);
    k_transpose<<<dim3(BATCH / 32, BATCH / 32), tb>>>(W1,         256, p_W1aT, BATCH);
    k_transpose<<<dim3(BATCH / 32, BATCH / 32), tb>>>(W1 + BATCH, 256, p_W1bT, BATCH);

    // 2) U = W1a@img + b1, V = W1b@text  (stored transposed)
    k_uv<<<2 * DIM, BATCH>>>(b1);

    // 3) per-edge MLP + scatter-accumulate
    k_edge<<<E_NUM / 8, 256>>>(src, tgt, w2, b2);

    // 4) transpose accumulators into the output layout
    k_writeout<<<dim3(BATCH / 32, DIM / 32, 2), tb>>>(out);
}

// round 2
// speedup vs baseline: 1.6539x; 1.6539x over previous
#include <cuda_runtime.h>
#include <math.h>

// Problem constants (fixed by the dataset)
#define E_NUM 32768
#define BATCH 128     // == H
#define DIM   1024    // IMG_DIM == TXT_DIM

// ---- device scratch (allocation-free: __device__ globals) ----
__device__ float g_imgT [DIM * BATCH];   // img^T  [i][b]
__device__ float g_txtT [DIM * BATCH];   // text^T [t][b]
__device__ float g_W1aT [BATCH * BATCH]; // W1[:, :128]^T  -> [b][j]
__device__ float g_W1bT [BATCH * BATCH]; // W1[:, 128:]^T  -> [b][j]
__device__ float g_UT   [DIM * BATCH];   // (W1a @ img + b1)^T : [s][j]
__device__ float g_VT   [DIM * BATCH];   // (W1b @ text)^T     : [t][j]
__device__ float g_oImgT[DIM * BATCH];   // attended_img^T [i][b]
__device__ float g_oTxtT[DIM * BATCH];   // attended_text^T [t][b]

// ---- fused transposes: one launch, flat block id ----
// blocks [0,128):   img  [128 x 1024] -> g_imgT [1024 x 128]
// blocks [128,256): txt  [128 x 1024] -> g_txtT [1024 x 128]
// blocks [256,272): W1a  (W1[:, :128]) -> g_W1aT [128 x 128]
// blocks [272,288): W1b  (W1[:, 128:]) -> g_W1bT [128 x 128]
__global__ void k_prep(const float* __restrict__ img, const float* __restrict__ txt,
                       const float* __restrict__ W1) {
    __shared__ float tile[32][33];
    int id = blockIdx.x;

    const float* in;
    float* out;
    int in_stride, bx, by;
    if (id < 256) {
        bool isTxt = id >= 128;
        int lid = id & 127;
        in = (isTxt ? txt : img);
        out = isTxt ? g_txtT : g_imgT;
        in_stride = DIM;
        bx = lid & 31;       // input col block (0..31)
        by = lid >> 5;       // input row block (0..3)
    } else {
        bool isB = id >= 272;
        int lid = (id - 256) & 15;
        in = W1 + (isB ? BATCH : 0);
        out = isB ? g_W1bT : g_W1aT;
        in_stride = 2 * BATCH;
        bx = lid & 3;
        by = lid >> 2;
    }

    int x = bx * 32 + threadIdx.x;   // input col
    int y = by * 32 + threadIdx.y;   // input row
    tile[threadIdx.y][threadIdx.x] = in[(long)y * in_stride + x];
    __syncthreads();
    int ox = by * 32 + threadIdx.x;  // output col = input row
    int oy = bx * 32 + threadIdx.y;  // output row = input col
    out[(long)oy * BATCH + ox] = tile[threadIdx.x][threadIdx.y];
}

// ---- UT[s][j] = b1[j] + sum_b W1aT[b][j]*imgT[s][b]
//      VT[t][j] =         sum_b W1bT[b][j]*txtT[t][b]
// Also zeroes the output accumulators (thread count == element count per array).
__global__ void k_uv(const float* __restrict__ b1) {
    int  col = blockIdx.x & (DIM - 1);
    bool isV = blockIdx.x >= DIM;
    int  j   = threadIdx.x;

    // fused accumulator zeroing for the scatter phase
    int zidx = col * BATCH + j;
    (isV ? g_oTxtT : g_oImgT)[zidx] = 0.0f;

    const float* x  = (isV ? g_txtT : g_imgT) + col * BATCH;
    const float* Wt =  isV ? g_W1bT : g_W1aT;

    __shared__ float xs[BATCH];
    xs[j] = x[j];
    __syncthreads();

    float acc = isV ? 0.0f : b1[j];
#pragma unroll 16
    for (int b = 0; b < BATCH; ++b)
        acc = fmaf(Wt[b * BATCH + j], xs[b], acc);

    (isV ? g_VT : g_UT)[col * BATCH + j] = acc;
}

// ---- per-edge: a = sigmoid(w2 . relu(UT[s] + VT[t]) + b2), then scatter:
//      oImgT[s][:] += a * txtT[t][:];  oTxtT[t][:] += a * imgT[s][:]
// One warp per edge, float4 per lane, vectorized red.global.v4.f32.add (sm_90+).
__global__ void k_edge(const int* __restrict__ src, const int* __restrict__ tgt,
                       const float* __restrict__ w2, const float* __restrict__ b2) {
    int warp = threadIdx.x >> 5;
    int lane = threadIdx.x & 31;
    int e    = blockIdx.x * 8 + warp;

    int s = src[e];
    int t = tgt[e];

    float4 u = reinterpret_cast<const float4*>(g_UT + s * BATCH)[lane];
    float4 v = reinterpret_cast<const float4*>(g_VT + t * BATCH)[lane];
    float4 w = reinterpret_cast<const float4*>(w2)[lane];

    float h0 = fmaxf(u.x + v.x, 0.0f);
    float h1 = fmaxf(u.y + v.y, 0.0f);
    float h2 = fmaxf(u.z + v.z, 0.0f);
    float h3 = fmaxf(u.w + v.w, 0.0f);

    float p = fmaf(h0, w.x, fmaf(h1, w.y, fmaf(h2, w.z, h3 * w.w)));
#pragma unroll
    for (int off = 16; off; off >>= 1)
        p += __shfl_xor_sync(0xffffffffu, p, off);

    float a = 1.0f / (1.0f + __expf(-(p + b2[0])));

    float4 tx = reinterpret_cast<const float4*>(g_txtT + t * BATCH)[lane];
    float4 im = reinterpret_cast<const float4*>(g_imgT + s * BATCH)[lane];

    float* oi = g_oImgT + s * BATCH + lane * 4;
    float* ot = g_oTxtT + t * BATCH + lane * 4;

    asm volatile("red.global.v4.f32.add [%0], {%1, %2, %3, %4};"
                 :: "l"(oi), "f"(a * tx.x), "f"(a * tx.y), "f"(a * tx.z), "f"(a * tx.w)
                 : "memory");
    asm volatile("red.global.v4.f32.add [%0], {%1, %2, %3, %4};"
                 :: "l"(ot), "f"(a * im.x), "f"(a * im.y), "f"(a * im.z), "f"(a * im.w)
                 : "memory");
}

// ---- final transpose of accumulators into the output layout ----
__global__ void k_writeout(float* __restrict__ out) {
    // out[0 .. 128*1024)          = attended_img  [b][i] = oImgT[i][b]
    // out[128*1024 .. 2*128*1024) = attended_text [b][t] = oTxtT[t][b]
    __shared__ float tile[32][33];
    bool second = blockIdx.z != 0;
    const float* in = second ? g_oTxtT : g_oImgT;
    float* o = out + (second ? (size_t)BATCH * DIM : 0);

    int x = blockIdx.x * 32 + threadIdx.x;   // b  (input col, 0..127)
    int y = blockIdx.y * 32 + threadIdx.y;   // i/t (input row, 0..1023)
    tile[threadIdx.y][threadIdx.x] = in[(long)y * BATCH + x];
    __syncthreads();
    int ox = blockIdx.y * 32 + threadIdx.x;  // i/t
    int oy = blockIdx.x * 32 + threadIdx.y;  // b
    o[(long)oy * DIM + ox] = tile[threadIdx.x][threadIdx.y];
}

extern "C" void kernel_launch(void* const* d_in, const int* in_sizes, int n_in,
                              void* d_out, int out_size) {
    const float* img = (const float*)d_in[0];   // [128, 1024]
    const float* txt = (const float*)d_in[1];   // [128, 1024]
    const int*   src = (const int*)  d_in[2];   // [32768]
    const int*   tgt = (const int*)  d_in[3];   // [32768]
    const float* W1  = (const float*)d_in[4];   // [128, 256]
    const float* b1  = (const float*)d_in[5];   // [128]
    const float* w2  = (const float*)d_in[6];   // [128]
    const float* b2  = (const float*)d_in[7];   // [1]
    float* out = (float*)d_out;                 // [2 * 128 * 1024]

    dim3 tb(32, 32);

    // 1) fused transposes (img, txt, W1a, W1b)
    k_prep<<<288, tb>>>(img, txt, W1);

    // 2) U/V GEMMs + accumulator zeroing
    k_uv<<<2 * DIM, BATCH>>>(b1);

    // 3) per-edge MLP + vectorized scatter-accumulate
    k_edge<<<E_NUM / 8, 256>>>(src, tgt, w2, b2);

    // 4) transpose accumulators into the output layout
    k_writeout<<<dim3(BATCH / 32, DIM / 32, 2), tb>>>(out);
}